// round 13
// baseline (speedup 1.0000x reference)
#include <cuda_runtime.h>
#include <cuda_bf16.h>
#include <math.h>

#define DDIM 128
#define KCODES 256
#define BM 128
#define NB_MAX 8192
#define FIXCAP 131072

typedef unsigned int u32;

// ----------------- device scratch (no allocations allowed) -----------------
__device__ __align__(16) float g_en[KCODES * DDIM];          // normalized codebook fp32
__device__ __align__(16) unsigned char g_bimg[KCODES * 256]; // bf16 codebook image, swizzled
__device__ float g_part[NB_MAX * KCODES];
__device__ float g_part2[32 * KCODES];
__device__ int   g_cnt;
__device__ int   g_fix[FIXCAP];

// ----------------- helpers -----------------
// XOR swizzle: rows are 256B (128 bf16); 16B granule index XORed with row&7.
__device__ __forceinline__ u32 sw_off(u32 row, u32 byte) {
    return row * 256u + ((((byte >> 4) ^ (row & 7u)) << 4) | (byte & 15u));
}
__device__ __forceinline__ u32 smem_u32(const void* p) {
    u32 a; asm("{ .reg .u64 t; cvta.to.shared.u64 t, %1; cvt.u32.u64 %0, t; }" : "=r"(a) : "l"(p));
    return a;
}
__device__ __forceinline__ void ldsm4(u32& r0, u32& r1, u32& r2, u32& r3, u32 a) {
    asm volatile("ldmatrix.sync.aligned.m8n8.x4.shared.b16 {%0,%1,%2,%3}, [%4];"
        : "=r"(r0), "=r"(r1), "=r"(r2), "=r"(r3) : "r"(a));
}
__device__ __forceinline__ void hmma(float* c, u32 a0, u32 a1, u32 a2, u32 a3, u32 b0, u32 b1) {
    asm volatile("mma.sync.aligned.m16n8k16.row.col.f32.bf16.bf16.f32 "
        "{%0,%1,%2,%3}, {%4,%5,%6,%7}, {%8,%9}, {%0,%1,%2,%3};"
        : "+f"(c[0]), "+f"(c[1]), "+f"(c[2]), "+f"(c[3])
        : "r"(a0), "r"(a1), "r"(a2), "r"(a3), "r"(b0), "r"(b1));
}
__device__ __forceinline__ u32 bpack(__nv_bfloat16 x, __nv_bfloat16 y) {
    __nv_bfloat162 h = __halves2bfloat162(x, y);
    return *(u32*)&h;
}

// smem layout (bytes from dynamic smem base)
#define SM_B    0         // 65536 (codebook bf16 image)
#define SM_A    65536     // 32768 (z tile bf16 image)
#define SM_SQ   98304     // 128 f : row sumsq
#define SM_SC   98816     // 128 f : per-row exp scale
#define SM_SUM  99328     // [2][128] f : per-side sum-exp
#define SM_B1   100352    // [2][128] f : per-side best logit
#define SM_B2   101376    // [2][128] f : per-side 2nd logit
#define SM_IDX  102400    // [2][128] i : per-side argmax
#define SM_INV  103424    // 128 f : 1/S
#define SM_IDXF 103936    // 128 i : final argmax
#define SM_PS   104448    // [16][128] f : per-warp col prob sums
#define SMEM_SZ 112640

// ---------------------------------------------------------------------------
// prep: e_n fp32 + swizzled bf16 codebook image + reset fix counter
// ---------------------------------------------------------------------------
__global__ void prep_kernel(const float* __restrict__ emb) {
    int k = threadIdx.x;                 // one code per thread (256)
    if (k == 0) g_cnt = 0;
    const float* row = emb + k * DDIM;
    float ss = 0.f;
    #pragma unroll 8
    for (int d = 0; d < DDIM; d++) { float x = row[d]; ss = fmaf(x, x, ss); }
    float inv = 1.0f / fmaxf(sqrtf(ss), 1e-12f);
    for (int d = 0; d < DDIM; d++) {
        float en = row[d] * inv;
        g_en[k * DDIM + d] = en;
        u32 off = sw_off((u32)k, (u32)(d * 2));
        *(__nv_bfloat16*)(g_bimg + off) = __float2bfloat16_rn(en);
    }
}

// ---------------------------------------------------------------------------
// main: persistent CTAs, 512 thr. Per 128-row tile: single bf16 HMMA GEMM
// (register accumulators) -> softmax/argmax/top2 epilogue + z_q gather.
// warp w: rows (w&7)*16..+15, codes (w>>3)*128..+127.
// ---------------------------------------------------------------------------
__global__ void __launch_bounds__(512, 1)
main_kernel(const float* __restrict__ z, const float* __restrict__ emb,
            const float* __restrict__ scale_p, float* __restrict__ out,
            int N, int nb)
{
    extern __shared__ unsigned char sm[];
    const u32 smb = smem_u32(sm);
    float* sq   = (float*)(sm + SM_SQ);
    float* sSc  = (float*)(sm + SM_SC);
    float* sSum = (float*)(sm + SM_SUM);
    float* sB1  = (float*)(sm + SM_B1);
    float* sB2  = (float*)(sm + SM_B2);
    int*   sIdx = (int*)(sm + SM_IDX);
    float* sInv = (float*)(sm + SM_INV);
    int*   sIdxF= (int*)(sm + SM_IDXF);
    float* sPS  = (float*)(sm + SM_PS);

    const int tid  = threadIdx.x;
    const int wid  = tid >> 5, lane = tid & 31;
    const int side = wid >> 3, rb = wid & 7;
    const int g    = lane >> 2, t = lane & 3;
    const float scl = *scale_p;

    // copy codebook image to smem once (65536 B)
    {
        const float4* src = (const float4*)g_bimg;
        float4* dst = (float4*)(sm + SM_B);
        #pragma unroll
        for (int i = 0; i < 8; i++) dst[i * 512 + tid] = src[i * 512 + tid];
    }

    // per-lane ldmatrix address components
    const u32 aRow = (u32)(rb * 16 + (lane & 15));
    const u32 aKad = (u32)((lane >> 4) * 16);
    const u32 bRow = (u32)(side * 128 + (lane & 7) + (lane >> 4) * 8);
    const u32 bKad = (u32)(((lane >> 3) & 1) * 16);
    const u32 aBase = smb + SM_A;
    const u32 bBase = smb + SM_B;

    __syncthreads();

    for (int bid = blockIdx.x; bid < nb; bid += gridDim.x) {
        const int m0 = bid * BM;

        // ---- convert z tile -> bf16 image + row sumsq (warp per row) ----
        #pragma unroll
        for (int it = 0; it < 8; it++) {
            int row = it * 16 + wid;
            float4 v = ((const float4*)(z + (size_t)(m0 + row) * DDIM))[lane];
            float ss = fmaf(v.x, v.x, fmaf(v.y, v.y, fmaf(v.z, v.z, v.w * v.w)));
            #pragma unroll
            for (int o = 16; o; o >>= 1) ss += __shfl_xor_sync(~0u, ss, o);
            if (lane == 0) sq[row] = ss;
            u32 off = sw_off((u32)row, (u32)(lane * 8));
            *(uint2*)(sm + SM_A + off) = make_uint2(
                bpack(__float2bfloat16_rn(v.x), __float2bfloat16_rn(v.y)),
                bpack(__float2bfloat16_rn(v.z), __float2bfloat16_rn(v.w)));
        }
        __syncthreads();
        if (tid < 128) sSc[tid] = scl / fmaxf(sqrtf(sq[tid]), 1e-12f);

        // ---- GEMM: single bf16 product, 8 k-steps ----
        float acc[16][4];
        #pragma unroll
        for (int n = 0; n < 16; n++) {
            acc[n][0] = 0.f; acc[n][1] = 0.f; acc[n][2] = 0.f; acc[n][3] = 0.f;
        }
        #pragma unroll 1
        for (int ks = 0; ks < 8; ks++) {
            u32 a0, a1, a2, a3;
            ldsm4(a0, a1, a2, a3, aBase + sw_off(aRow, (u32)(ks * 32) + aKad));
            #pragma unroll
            for (int p = 0; p < 8; p++) {
                u32 b0, b1, b2, b3;
                ldsm4(b0, b1, b2, b3, bBase + sw_off(bRow + (u32)(p * 16), (u32)(ks * 32) + bKad));
                hmma(acc[2 * p],     a0, a1, a2, a3, b0, b1);
                hmma(acc[2 * p + 1], a0, a1, a2, a3, b2, b3);
            }
        }
        __syncthreads();   // sSc visible everywhere

        // ---- pass 1: top-2/argmax on logits, exps (overwrite acc), sums ----
        const int row0 = rb * 16 + g, row1 = row0 + 8;
        const float sc0 = sSc[row0], sc1 = sSc[row1];
        float s0 = 0.f, s1 = 0.f;
        float a1v = -1e30f, a2v = -1e30f, b1v = -1e30f, b2v = -1e30f;
        int ai = 0, bi = 0;
        const int colB = side * 128 + t * 2;
        #pragma unroll
        for (int n = 0; n < 16; n++) {
            #pragma unroll
            for (int b = 0; b < 2; b++) {
                int c = colB + 8 * n + b;
                float l0 = acc[n][b];
                if (l0 > a1v) { a2v = a1v; a1v = l0; ai = c; } else a2v = fmaxf(a2v, l0);
                float e0 = __expf(sc0 * l0); acc[n][b] = e0; s0 += e0;
                float l1 = acc[n][b + 2];
                if (l1 > b1v) { b2v = b1v; b1v = l1; bi = c; } else b2v = fmaxf(b2v, l1);
                float e1 = __expf(sc1 * l1); acc[n][b + 2] = e1; s1 += e1;
            }
        }
        #pragma unroll
        for (int o = 1; o < 4; o <<= 1) {
            s0 += __shfl_xor_sync(~0u, s0, o);
            s1 += __shfl_xor_sync(~0u, s1, o);
            float ov, o2; int oi;
            ov = __shfl_xor_sync(~0u, a1v, o); o2 = __shfl_xor_sync(~0u, a2v, o); oi = __shfl_xor_sync(~0u, ai, o);
            if (ov > a1v || (ov == a1v && oi < ai)) { a2v = fmaxf(a1v, o2); a1v = ov; ai = oi; }
            else a2v = fmaxf(a2v, ov);
            ov = __shfl_xor_sync(~0u, b1v, o); o2 = __shfl_xor_sync(~0u, b2v, o); oi = __shfl_xor_sync(~0u, bi, o);
            if (ov > b1v || (ov == b1v && oi < bi)) { b2v = fmaxf(b1v, o2); b1v = ov; bi = oi; }
            else b2v = fmaxf(b2v, ov);
        }
        if (t == 0) {
            sSum[side * 128 + row0] = s0; sB1[side * 128 + row0] = a1v;
            sB2[side * 128 + row0] = a2v; sIdx[side * 128 + row0] = ai;
            sSum[side * 128 + row1] = s1; sB1[side * 128 + row1] = b1v;
            sB2[side * 128 + row1] = b2v; sIdx[side * 128 + row1] = bi;
        }
        __syncthreads();

        // ---- combine sides, near-tie guard (logit gap), write index ----
        if (tid < 128) {
            int r = tid;
            float S = sSum[r] + sSum[128 + r];
            float x1 = sB1[r], x2 = sB2[r]; int xi = sIdx[r];
            float y1 = sB1[128 + r], y2 = sB2[128 + r]; int yi = sIdx[128 + r];
            float t1, t2; int ti;
            if (y1 > x1) { t1 = y1; ti = yi; t2 = fmaxf(x1, y2); }
            else         { t1 = x1; ti = xi; t2 = fmaxf(x2, y1); }  // tie -> lower side
            float thresh = 2e-3f * sqrtf(sq[r]);   // ~25 sigma of bf16 logit error
            if (t1 - t2 < thresh) {
                int p = atomicAdd(&g_cnt, 1);
                if (p < FIXCAP) g_fix[p] = m0 + r;
            }
            sInv[r] = 1.0f / S;
            sIdxF[r] = ti;
            out[(size_t)N * DDIM + (m0 + r)] = (float)ti;
        }
        __syncthreads();

        // ---- pass 2: prob column sums (acc holds exps) ----
        {
            float ri0 = sInv[row0], ri1 = sInv[row1];
            #pragma unroll
            for (int n = 0; n < 16; n++) {
                float c0 = acc[n][0] * ri0 + acc[n][2] * ri1;
                float c1 = acc[n][1] * ri0 + acc[n][3] * ri1;
                #pragma unroll
                for (int o = 4; o < 32; o <<= 1) {
                    c0 += __shfl_xor_sync(~0u, c0, o);
                    c1 += __shfl_xor_sync(~0u, c1, o);
                }
                if (g == 0) {
                    sPS[wid * 128 + 8 * n + 2 * t]     = c0;
                    sPS[wid * 128 + 8 * n + 2 * t + 1] = c1;
                }
            }
        }
        // ---- z_q gather (warp per row, coalesced; emb is L2-resident) ----
        #pragma unroll
        for (int it = 0; it < 8; it++) {
            int row = it * 16 + wid;
            int ci = sIdxF[row];
            const float4* src = (const float4*)(emb + (size_t)ci * DDIM);
            float4* dst = (float4*)(out + (size_t)(m0 + row) * DDIM);
            dst[lane] = src[lane];
        }
        __syncthreads();
        if (tid < 256) {
            int col = tid;
            int wb = (col >> 7) * 8, cc = col & 127;
            float s = 0.f;
            #pragma unroll
            for (int w8 = 0; w8 < 8; w8++) s += sPS[(wb + w8) * 128 + cc];
            g_part[(size_t)bid * KCODES + col] = s;
        }
        __syncthreads();
    }
}

// ---------------------------------------------------------------------------
// fixup: recompute near-tie rows with exact sequential fp32 dots.
// ---------------------------------------------------------------------------
__global__ void fix_kernel(const float* __restrict__ z, const float* __restrict__ emb,
                           float* __restrict__ out, int N)
{
    int cnt = g_cnt; if (cnt > FIXCAP) cnt = FIXCAP;
    const int lane = threadIdx.x & 31;
    const int gw = (blockIdx.x * blockDim.x + threadIdx.x) >> 5;
    const int nw = (gridDim.x * blockDim.x) >> 5;
    const unsigned FULL = 0xFFFFFFFFu;

    for (int w = gw; w < cnt; w += nw) {
        const int m = g_fix[w];
        const float* zr = z + (size_t)m * DDIM;
        float bv = -1e30f; int bi = 0;
        #pragma unroll 1
        for (int i = 0; i < 8; i++) {
            const int c = lane + 32 * i;
            const float* er = g_en + (size_t)c * DDIM;
            float acc = 0.f;
            #pragma unroll 8
            for (int d = 0; d < DDIM; d++) acc = fmaf(zr[d], er[d], acc);
            if (acc > bv) { bv = acc; bi = c; }
        }
        #pragma unroll
        for (int o = 1; o < 32; o <<= 1) {
            float ov = __shfl_xor_sync(FULL, bv, o);
            int   oi = __shfl_xor_sync(FULL, bi, o);
            if (ov > bv || (ov == bv && oi < bi)) { bv = ov; bi = oi; }
        }
        if (lane == 0) out[(size_t)N * DDIM + m] = (float)bi;
        const float4* src = (const float4*)(emb + (size_t)bi * DDIM);
        float4* dst = (float4*)(out + (size_t)m * DDIM);
        dst[lane] = src[lane];
    }
}

// ---------------------------------------------------------------------------
__global__ void reduce1_kernel(int nb) {
    int r = blockIdx.x, k = threadIdx.x;  // 32 blocks x 256 threads
    float s0 = 0.f, s1 = 0.f, s2 = 0.f, s3 = 0.f;
    int j = r;
    for (; j + 96 < nb; j += 128) {
        s0 += g_part[(size_t)j * 256 + k];
        s1 += g_part[(size_t)(j + 32) * 256 + k];
        s2 += g_part[(size_t)(j + 64) * 256 + k];
        s3 += g_part[(size_t)(j + 96) * 256 + k];
    }
    for (; j < nb; j += 32) s0 += g_part[(size_t)j * 256 + k];
    g_part2[r * KCODES + k] = (s0 + s1) + (s2 + s3);
}

__global__ void ppl_kernel(float* __restrict__ out, float invN, size_t off) {
    int k = threadIdx.x;
    float a = 0.f;
    #pragma unroll
    for (int r = 0; r < 32; r++) a += g_part2[r * KCODES + k];
    a *= invN;
    float t = -a * logf(a + 1e-10f);
    __shared__ float red[8];
    #pragma unroll
    for (int o = 16; o; o >>= 1) t += __shfl_xor_sync(0xFFFFFFFFu, t, o);
    if ((k & 31) == 0) red[k >> 5] = t;
    __syncthreads();
    if (k < 8) {
        float v = red[k];
        #pragma unroll
        for (int o = 4; o; o >>= 1) v += __shfl_xor_sync(0xFFu, v, o);
        if (k == 0) out[off] = expf(v);
    }
}

// ---------------------------------------------------------------------------
extern "C" void kernel_launch(void* const* d_in, const int* in_sizes, int n_in,
                              void* d_out, int out_size) {
    const float* z     = (const float*)d_in[0];
    const float* emb   = (const float*)d_in[1];
    const float* scale = (const float*)d_in[2];
    float* out = (float*)d_out;

    const int N  = in_sizes[0] / DDIM;
    const int nb = N / BM;

    cudaFuncSetAttribute(main_kernel, cudaFuncAttributeMaxDynamicSharedMemorySize, SMEM_SZ);

    prep_kernel<<<1, 256>>>(emb);
    main_kernel<<<148, 512, SMEM_SZ>>>(z, emb, scale, out, N, nb);
    fix_kernel<<<256, 256>>>(z, emb, out, N);
    reduce1_kernel<<<32, 256>>>(nb);
    ppl_kernel<<<1, 256>>>(out, 1.0f / (float)N, (size_t)N * DDIM + (size_t)N);
}

// round 16
// speedup vs baseline: 2.7992x; 2.7992x over previous
#include <cuda_runtime.h>
#include <cuda_bf16.h>
#include <math.h>

#define DDIM 128
#define KCODES 256
#define BM 128
#define NB_MAX 8192
#define FIXCAP 131072

typedef unsigned int u32;
typedef unsigned long long u64;

// ----------------- device scratch (no allocations allowed) -----------------
__device__ __align__(16) float g_en[KCODES * DDIM];          // normalized codebook fp32 [k][d]
__device__ __align__(16) float g_enT[DDIM * KCODES];         // transposed [d][k]
__device__ __align__(16) unsigned char g_bimg[KCODES * 256]; // bf16 codebook image, swizzled
__device__ float g_part[NB_MAX * KCODES];
__device__ float g_part2[32 * KCODES];
__device__ int   g_cnt;
__device__ int   g_fix[FIXCAP];

// ----------------- helpers -----------------
__device__ __forceinline__ u32 sw_off(u32 row, u32 byte) {
    return row * 256u + ((((byte >> 4) ^ (row & 7u)) << 4) | (byte & 15u));
}
__device__ __forceinline__ u32 smem_u32(const void* p) {
    u32 a; asm("{ .reg .u64 t; cvta.to.shared.u64 t, %1; cvt.u32.u64 %0, t; }" : "=r"(a) : "l"(p));
    return a;
}
__device__ __forceinline__ void ldsm4(u32& r0, u32& r1, u32& r2, u32& r3, u32 a) {
    asm volatile("ldmatrix.sync.aligned.m8n8.x4.shared.b16 {%0,%1,%2,%3}, [%4];"
        : "=r"(r0), "=r"(r1), "=r"(r2), "=r"(r3) : "r"(a));
}
__device__ __forceinline__ void hmma(float* c, u32 a0, u32 a1, u32 a2, u32 a3, u32 b0, u32 b1) {
    asm volatile("mma.sync.aligned.m16n8k16.row.col.f32.bf16.bf16.f32 "
        "{%0,%1,%2,%3}, {%4,%5,%6,%7}, {%8,%9}, {%0,%1,%2,%3};"
        : "+f"(c[0]), "+f"(c[1]), "+f"(c[2]), "+f"(c[3])
        : "r"(a0), "r"(a1), "r"(a2), "r"(a3), "r"(b0), "r"(b1));
}
__device__ __forceinline__ u32 bpack(__nv_bfloat16 x, __nv_bfloat16 y) {
    __nv_bfloat162 h = __halves2bfloat162(x, y);
    return *(u32*)&h;
}
// order-preserving float->u32 (max & first-index tie-break via packed u64)
__device__ __forceinline__ u32 fsort(float f) {
    u32 u = __float_as_uint(f);
    return (u & 0x80000000u) ? ~u : (u | 0x80000000u);
}

// ----- main kernel smem layout -----
#define SM_B    0
#define SM_A    65536
#define SM_SQ   98304
#define SM_SC   98816
#define SM_SUM  99328
#define SM_B1   100352
#define SM_B2   101376
#define SM_IDX  102400
#define SM_INV  103424
#define SM_IDXF 103936
#define SM_PS   104448
#define SMEM_SZ 112640

// ----- fix kernel smem layout -----
#define FX_ET   0              // 131072 : transposed codebook
#define FX_Z    131072         // 4*512  : 4 z rows
#define FX_BEST 133120         // 4*8    : packed argmax
#define FX_IDX  133152         // 4*4
#define FX_SZ   133184

// ---------------------------------------------------------------------------
// prep: e_n fp32 + transposed copy + swizzled bf16 image + reset counter
// ---------------------------------------------------------------------------
__global__ void prep_kernel(const float* __restrict__ emb) {
    int k = threadIdx.x;                 // one code per thread (256)
    if (k == 0) g_cnt = 0;
    const float* row = emb + k * DDIM;
    float ss = 0.f;
    #pragma unroll 8
    for (int d = 0; d < DDIM; d++) { float x = row[d]; ss = fmaf(x, x, ss); }
    float inv = 1.0f / fmaxf(sqrtf(ss), 1e-12f);
    for (int d = 0; d < DDIM; d++) {
        float en = row[d] * inv;
        g_en[k * DDIM + d] = en;
        g_enT[d * KCODES + k] = en;      // coalesced across threads
        u32 off = sw_off((u32)k, (u32)(d * 2));
        *(__nv_bfloat16*)(g_bimg + off) = __float2bfloat16_rn(en);
    }
}

// ---------------------------------------------------------------------------
// main: persistent CTAs, 512 thr. Single bf16 HMMA GEMM (full unroll) ->
// softmax/argmax/top2 epilogue + z_q gather + avg_prob partials.
// warp w: rows (w&7)*16..+15, codes (w>>3)*128..+127.
// ---------------------------------------------------------------------------
__global__ void __launch_bounds__(512, 1)
main_kernel(const float* __restrict__ z, const float* __restrict__ emb,
            const float* __restrict__ scale_p, float* __restrict__ out,
            int N, int nb)
{
    extern __shared__ unsigned char sm[];
    const u32 smb = smem_u32(sm);
    float* sq   = (float*)(sm + SM_SQ);
    float* sSc  = (float*)(sm + SM_SC);
    float* sSum = (float*)(sm + SM_SUM);
    float* sB1  = (float*)(sm + SM_B1);
    float* sB2  = (float*)(sm + SM_B2);
    int*   sIdx = (int*)(sm + SM_IDX);
    float* sInv = (float*)(sm + SM_INV);
    int*   sIdxF= (int*)(sm + SM_IDXF);
    float* sPS  = (float*)(sm + SM_PS);

    const int tid  = threadIdx.x;
    const int wid  = tid >> 5, lane = tid & 31;
    const int side = wid >> 3, rb = wid & 7;
    const int g    = lane >> 2, t = lane & 3;
    const float scl = *scale_p;

    // copy codebook image to smem once
    {
        const float4* src = (const float4*)g_bimg;
        float4* dst = (float4*)(sm + SM_B);
        #pragma unroll
        for (int i = 0; i < 8; i++) dst[i * 512 + tid] = src[i * 512 + tid];
    }

    const u32 aRow = (u32)(rb * 16 + (lane & 15));
    const u32 aKad = (u32)((lane >> 4) * 16);
    const u32 bRow = (u32)(side * 128 + (lane & 7) + (lane >> 4) * 8);
    const u32 bKad = (u32)(((lane >> 3) & 1) * 16);
    const u32 aBase = smb + SM_A;
    const u32 bBase = smb + SM_B;

    __syncthreads();

    for (int bid = blockIdx.x; bid < nb; bid += gridDim.x) {
        const int m0 = bid * BM;

        // ---- convert z tile -> bf16 image + row sumsq (warp per row) ----
        #pragma unroll
        for (int it = 0; it < 8; it++) {
            int row = it * 16 + wid;
            float4 v = ((const float4*)(z + (size_t)(m0 + row) * DDIM))[lane];
            float ss = fmaf(v.x, v.x, fmaf(v.y, v.y, fmaf(v.z, v.z, v.w * v.w)));
            #pragma unroll
            for (int o = 16; o; o >>= 1) ss += __shfl_xor_sync(~0u, ss, o);
            if (lane == 0) sq[row] = ss;
            u32 off = sw_off((u32)row, (u32)(lane * 8));
            *(uint2*)(sm + SM_A + off) = make_uint2(
                bpack(__float2bfloat16_rn(v.x), __float2bfloat16_rn(v.y)),
                bpack(__float2bfloat16_rn(v.z), __float2bfloat16_rn(v.w)));
        }
        __syncthreads();
        if (tid < 128) sSc[tid] = scl / fmaxf(sqrtf(sq[tid]), 1e-12f);

        // ---- GEMM: single bf16 product, fully unrolled ----
        float acc[16][4];
        #pragma unroll
        for (int n = 0; n < 16; n++) {
            acc[n][0] = 0.f; acc[n][1] = 0.f; acc[n][2] = 0.f; acc[n][3] = 0.f;
        }
        #pragma unroll
        for (int ks = 0; ks < 8; ks++) {
            u32 a0, a1, a2, a3;
            ldsm4(a0, a1, a2, a3, aBase + sw_off(aRow, (u32)(ks * 32) + aKad));
            #pragma unroll
            for (int p = 0; p < 8; p++) {
                u32 b0, b1, b2, b3;
                ldsm4(b0, b1, b2, b3, bBase + sw_off(bRow + (u32)(p * 16), (u32)(ks * 32) + bKad));
                hmma(acc[2 * p],     a0, a1, a2, a3, b0, b1);
                hmma(acc[2 * p + 1], a0, a1, a2, a3, b2, b3);
            }
        }
        __syncthreads();

        // ---- pass 1: top-2/argmax on logits, exps (overwrite acc), sums ----
        const int row0 = rb * 16 + g, row1 = row0 + 8;
        const float sc0 = sSc[row0], sc1 = sSc[row1];
        float s0 = 0.f, s1 = 0.f;
        float a1v = -1e30f, a2v = -1e30f, b1v = -1e30f, b2v = -1e30f;
        int ai = 0, bi = 0;
        const int colB = side * 128 + t * 2;
        #pragma unroll
        for (int n = 0; n < 16; n++) {
            #pragma unroll
            for (int b = 0; b < 2; b++) {
                int c = colB + 8 * n + b;
                float l0 = acc[n][b];
                if (l0 > a1v) { a2v = a1v; a1v = l0; ai = c; } else a2v = fmaxf(a2v, l0);
                float e0 = __expf(sc0 * l0); acc[n][b] = e0; s0 += e0;
                float l1 = acc[n][b + 2];
                if (l1 > b1v) { b2v = b1v; b1v = l1; bi = c; } else b2v = fmaxf(b2v, l1);
                float e1 = __expf(sc1 * l1); acc[n][b + 2] = e1; s1 += e1;
            }
        }
        #pragma unroll
        for (int o = 1; o < 4; o <<= 1) {
            s0 += __shfl_xor_sync(~0u, s0, o);
            s1 += __shfl_xor_sync(~0u, s1, o);
            float ov, o2; int oi;
            ov = __shfl_xor_sync(~0u, a1v, o); o2 = __shfl_xor_sync(~0u, a2v, o); oi = __shfl_xor_sync(~0u, ai, o);
            if (ov > a1v || (ov == a1v && oi < ai)) { a2v = fmaxf(a1v, o2); a1v = ov; ai = oi; }
            else a2v = fmaxf(a2v, ov);
            ov = __shfl_xor_sync(~0u, b1v, o); o2 = __shfl_xor_sync(~0u, b2v, o); oi = __shfl_xor_sync(~0u, bi, o);
            if (ov > b1v || (ov == b1v && oi < bi)) { b2v = fmaxf(b1v, o2); b1v = ov; bi = oi; }
            else b2v = fmaxf(b2v, ov);
        }
        if (t == 0) {
            sSum[side * 128 + row0] = s0; sB1[side * 128 + row0] = a1v;
            sB2[side * 128 + row0] = a2v; sIdx[side * 128 + row0] = ai;
            sSum[side * 128 + row1] = s1; sB1[side * 128 + row1] = b1v;
            sB2[side * 128 + row1] = b2v; sIdx[side * 128 + row1] = bi;
        }
        __syncthreads();

        // ---- combine sides, 7-sigma near-tie guard (PROVEN in R13) ----
        if (tid < 128) {
            int r = tid;
            float S = sSum[r] + sSum[128 + r];
            float x1 = sB1[r], x2 = sB2[r]; int xi = sIdx[r];
            float y1 = sB1[128 + r], y2 = sB2[128 + r]; int yi = sIdx[128 + r];
            float t1, t2; int ti;
            if (y1 > x1) { t1 = y1; ti = yi; t2 = fmaxf(x1, y2); }
            else         { t1 = x1; ti = xi; t2 = fmaxf(x2, y1); }
            float thresh = 2e-3f * sqrtf(sq[r]);   // ~7 sigma of bf16 logit error
            if (t1 - t2 < thresh) {
                int p = atomicAdd(&g_cnt, 1);
                if (p < FIXCAP) g_fix[p] = m0 + r;
            }
            sInv[r] = 1.0f / S;
            sIdxF[r] = ti;
            out[(size_t)N * DDIM + (m0 + r)] = (float)ti;
        }
        __syncthreads();

        // ---- pass 2: prob column sums ----
        {
            float ri0 = sInv[row0], ri1 = sInv[row1];
            #pragma unroll
            for (int n = 0; n < 16; n++) {
                float c0 = acc[n][0] * ri0 + acc[n][2] * ri1;
                float c1 = acc[n][1] * ri0 + acc[n][3] * ri1;
                #pragma unroll
                for (int o = 4; o < 32; o <<= 1) {
                    c0 += __shfl_xor_sync(~0u, c0, o);
                    c1 += __shfl_xor_sync(~0u, c1, o);
                }
                if (g == 0) {
                    sPS[wid * 128 + 8 * n + 2 * t]     = c0;
                    sPS[wid * 128 + 8 * n + 2 * t + 1] = c1;
                }
            }
        }
        // ---- z_q gather (warp per row, coalesced) ----
        #pragma unroll
        for (int it = 0; it < 8; it++) {
            int row = it * 16 + wid;
            int ci = sIdxF[row];
            const float4* src = (const float4*)(emb + (size_t)ci * DDIM);
            float4* dst = (float4*)(out + (size_t)(m0 + row) * DDIM);
            dst[lane] = src[lane];
        }
        __syncthreads();
        if (tid < 256) {
            int col = tid;
            int wb = (col >> 7) * 8, cc = col & 127;
            float s = 0.f;
            #pragma unroll
            for (int w8 = 0; w8 < 8; w8++) s += sPS[(wb + w8) * 128 + cc];
            g_part[(size_t)bid * KCODES + col] = s;
        }
        __syncthreads();
    }
}

// ---------------------------------------------------------------------------
// fixup: exact sequential-fp32 rescoring of flagged rows, COALESCED.
// Block stages the transposed codebook in smem; thread k owns code k;
// 4 rows per pass. Argmax tie-break = first max (packed u64 atomicMax).
// ---------------------------------------------------------------------------
__global__ void __launch_bounds__(256, 1)
fix_kernel(const float* __restrict__ z, const float* __restrict__ emb,
           float* __restrict__ out, int N)
{
    extern __shared__ unsigned char sm[];
    float* sET  = (float*)(sm + FX_ET);     // [128][256]
    float* sz   = (float*)(sm + FX_Z);      // [4][128]
    u64*   best = (u64*)(sm + FX_BEST);     // [4]
    int*   fidx = (int*)(sm + FX_IDX);      // [4]

    int cnt = g_cnt; if (cnt > FIXCAP) cnt = FIXCAP;
    if (cnt == 0) return;
    const int tid = threadIdx.x;

    // stage transposed codebook (128 KB, coalesced)
    {
        const float4* src = (const float4*)g_enT;
        float4* dst = (float4*)sET;
        #pragma unroll
        for (int i = 0; i < 32; i++) dst[i * 256 + tid] = src[i * 256 + tid];
    }
    __syncthreads();

    for (int base = blockIdx.x * 4; base < cnt; base += gridDim.x * 4) {
        const int nr = min(4, cnt - base);
        if (tid < 4) best[tid] = 0ull;
        if (tid < 128) {
            for (int j = 0; j < nr; j++) {
                int m = g_fix[base + j];
                sz[j * 128 + tid] = z[(size_t)m * DDIM + tid];
            }
        }
        __syncthreads();

        // thread k: exact fp32 dots (ascending d, matches reference decisions)
        float a0 = 0.f, a1 = 0.f, a2 = 0.f, a3 = 0.f;
        #pragma unroll 4
        for (int d = 0; d < DDIM; d++) {
            float e = sET[d * KCODES + tid];
            a0 = fmaf(sz[d], e, a0);
            a1 = fmaf(sz[128 + d], e, a1);
            a2 = fmaf(sz[256 + d], e, a2);
            a3 = fmaf(sz[384 + d], e, a3);
        }
        u64 inv = (u64)(255 - tid);
        atomicMax(&best[0], ((u64)fsort(a0) << 32) | inv);
        atomicMax(&best[1], ((u64)fsort(a1) << 32) | inv);
        atomicMax(&best[2], ((u64)fsort(a2) << 32) | inv);
        atomicMax(&best[3], ((u64)fsort(a3) << 32) | inv);
        __syncthreads();

        if (tid < nr) {
            int ki = 255 - (int)(best[tid] & 0xFFFFFFFFull);
            fidx[tid] = ki;
            int m = g_fix[base + tid];
            out[(size_t)N * DDIM + m] = (float)ki;
        }
        __syncthreads();

        // copy z_q rows: 64 threads x float2 per row
        {
            int j = tid >> 6, t2 = tid & 63;
            if (j < nr) {
                int m = g_fix[base + j];
                const float2* src = (const float2*)(emb + (size_t)fidx[j] * DDIM);
                float2* dst = (float2*)(out + (size_t)m * DDIM);
                dst[t2] = src[t2];
            }
        }
        __syncthreads();
    }
}

// ---------------------------------------------------------------------------
__global__ void reduce1_kernel(int nb) {
    int r = blockIdx.x, k = threadIdx.x;
    float s0 = 0.f, s1 = 0.f, s2 = 0.f, s3 = 0.f;
    int j = r;
    for (; j + 96 < nb; j += 128) {
        s0 += g_part[(size_t)j * 256 + k];
        s1 += g_part[(size_t)(j + 32) * 256 + k];
        s2 += g_part[(size_t)(j + 64) * 256 + k];
        s3 += g_part[(size_t)(j + 96) * 256 + k];
    }
    for (; j < nb; j += 32) s0 += g_part[(size_t)j * 256 + k];
    g_part2[r * KCODES + k] = (s0 + s1) + (s2 + s3);
}

__global__ void ppl_kernel(float* __restrict__ out, float invN, size_t off) {
    int k = threadIdx.x;
    float a = 0.f;
    #pragma unroll
    for (int r = 0; r < 32; r++) a += g_part2[r * KCODES + k];
    a *= invN;
    float t = -a * logf(a + 1e-10f);
    __shared__ float red[8];
    #pragma unroll
    for (int o = 16; o; o >>= 1) t += __shfl_xor_sync(0xFFFFFFFFu, t, o);
    if ((k & 31) == 0) red[k >> 5] = t;
    __syncthreads();
    if (k < 8) {
        float v = red[k];
        #pragma unroll
        for (int o = 4; o; o >>= 1) v += __shfl_xor_sync(0xFFu, v, o);
        if (k == 0) out[off] = expf(v);
    }
}

// ---------------------------------------------------------------------------
extern "C" void kernel_launch(void* const* d_in, const int* in_sizes, int n_in,
                              void* d_out, int out_size) {
    const float* z     = (const float*)d_in[0];
    const float* emb   = (const float*)d_in[1];
    const float* scale = (const float*)d_in[2];
    float* out = (float*)d_out;

    const int N  = in_sizes[0] / DDIM;
    const int nb = N / BM;

    cudaFuncSetAttribute(main_kernel, cudaFuncAttributeMaxDynamicSharedMemorySize, SMEM_SZ);
    cudaFuncSetAttribute(fix_kernel,  cudaFuncAttributeMaxDynamicSharedMemorySize, FX_SZ);

    prep_kernel<<<1, 256>>>(emb);
    main_kernel<<<148, 512, SMEM_SZ>>>(z, emb, scale, out, N, nb);
    fix_kernel<<<148, 256, FX_SZ>>>(z, emb, out, N);
    reduce1_kernel<<<32, 256>>>(nb);
    ppl_kernel<<<1, 256>>>(out, 1.0f / (float)N, (size_t)N * DDIM + (size_t)N);
}